// round 2
// baseline (speedup 1.0000x reference)
#include <cuda_runtime.h>

// Problem dims (fixed for this problem instance)
#define B_DIM 32
#define T_DIM 2048
#define I_DIM 256
#define H_DIM 512
#define M_DIM (B_DIM * T_DIM)   // 65536

#define ALPHA_MIN_F 0.8187307530779818f   // exp(-1/5)
#define ALPHA_MAX_F 0.9607894391523232f   // exp(-1/25)

// Scratch for the feedforward projection Wx: [M, H] fp32 = 128 MiB
__device__ float g_wx[(size_t)M_DIM * H_DIM];

// ---------------------------------------------------------------------------
// GEMM: g_wx[m, h] = sum_k A[m, k] * W[h, k]
//   A = x viewed as [M=65536, K=256] row-major (K contiguous)
//   W = [H=512, K=256] row-major (K contiguous)  -> "NT" gemm
// Tile: BM=128, BN=64, BK=16; 256 threads; each thread computes 8x4 outputs.
// ---------------------------------------------------------------------------
__global__ __launch_bounds__(256) void lif_gemm_kernel(
    const float* __restrict__ A,
    const float* __restrict__ W)
{
    constexpr int BM = 128, BN = 64, BK = 16, TM = 8, TN = 4;
    __shared__ __align__(16) float As[BK][BM];
    __shared__ __align__(16) float Bs[BK][BN];

    const int tid = threadIdx.x;
    const int tx  = tid & 15;   // 0..15 -> N direction (TN=4 each -> 64)
    const int ty  = tid >> 4;   // 0..15 -> M direction (TM=8 each -> 128)

    const int m0 = blockIdx.y * BM;
    const int n0 = blockIdx.x * BN;

    float acc[TM][TN];
    #pragma unroll
    for (int i = 0; i < TM; i++)
        #pragma unroll
        for (int j = 0; j < TN; j++)
            acc[i][j] = 0.0f;

    for (int k0 = 0; k0 < I_DIM; k0 += BK) {
        // --- load A tile: 128 rows x 16 cols = 512 float4, 2 per thread ---
        #pragma unroll
        for (int l = 0; l < 2; l++) {
            int lid = tid + l * 256;
            int row = lid >> 2;          // 0..127
            int c4  = (lid & 3) * 4;     // 0,4,8,12
            float4 v = *(const float4*)(&A[(size_t)(m0 + row) * I_DIM + k0 + c4]);
            As[c4 + 0][row] = v.x;
            As[c4 + 1][row] = v.y;
            As[c4 + 2][row] = v.z;
            As[c4 + 3][row] = v.w;
        }
        // --- load W tile: 64 rows x 16 cols = 256 float4, 1 per thread ---
        {
            int row = tid >> 2;          // 0..63
            int c4  = (tid & 3) * 4;
            float4 v = *(const float4*)(&W[(size_t)(n0 + row) * I_DIM + k0 + c4]);
            Bs[c4 + 0][row] = v.x;
            Bs[c4 + 1][row] = v.y;
            Bs[c4 + 2][row] = v.z;
            Bs[c4 + 3][row] = v.w;
        }
        __syncthreads();

        #pragma unroll
        for (int k = 0; k < BK; k++) {
            float4 a0 = *(const float4*)(&As[k][ty * TM]);
            float4 a1 = *(const float4*)(&As[k][ty * TM + 4]);
            float4 b0 = *(const float4*)(&Bs[k][tx * TN]);
            float ra[TM] = {a0.x, a0.y, a0.z, a0.w, a1.x, a1.y, a1.z, a1.w};
            float rb[TN] = {b0.x, b0.y, b0.z, b0.w};
            #pragma unroll
            for (int i = 0; i < TM; i++)
                #pragma unroll
                for (int j = 0; j < TN; j++)
                    acc[i][j] += ra[i] * rb[j];
        }
        __syncthreads();
    }

    // --- store ---
    #pragma unroll
    for (int i = 0; i < TM; i++) {
        int m = m0 + ty * TM + i;
        float4 v = make_float4(acc[i][0], acc[i][1], acc[i][2], acc[i][3]);
        *(float4*)(&g_wx[(size_t)m * H_DIM + n0 + tx * TN]) = v;
    }
}

// ---------------------------------------------------------------------------
// Scan: one thread per (b, h) chain; sequential over T with software-pipelined
// prefetch of the next U timesteps so DRAM loads overlap compute+stores.
// Coalescing: consecutive threads = consecutive h -> 512B contiguous per step.
// ---------------------------------------------------------------------------
__global__ __launch_bounds__(128) void lif_scan_kernel(
    const float* __restrict__ alpha_in,
    const float* __restrict__ u0,
    const float* __restrict__ s0,
    float* __restrict__ out)
{
    const int b = blockIdx.x >> 2;                       // 0..31
    const int h = (blockIdx.x & 3) * 128 + threadIdx.x;  // 0..511

    float a = alpha_in[h];
    a = fminf(fmaxf(a, ALPHA_MIN_F), ALPHA_MAX_F);
    const float bc = 1.0f - a;

    float u = u0[b * H_DIM + h];
    float s = s0[b * H_DIM + h];

    const float* __restrict__ wx = g_wx + (size_t)b * T_DIM * H_DIM + h;
    float* __restrict__ o = out + (size_t)b * T_DIM * H_DIM + h;

    constexpr int U = 8;
    float cur[U], nxt[U];

    #pragma unroll
    for (int i = 0; i < U; i++)
        cur[i] = wx[(size_t)i * H_DIM];

    for (int t0 = 0; t0 < T_DIM; t0 += U) {
        // prefetch next chunk (independent of recurrence state)
        if (t0 + U < T_DIM) {
            #pragma unroll
            for (int i = 0; i < U; i++)
                nxt[i] = wx[(size_t)(t0 + U + i) * H_DIM];
        }
        // sequential LIF update on current chunk
        #pragma unroll
        for (int i = 0; i < U; i++) {
            u = a * (u - s) + bc * cur[i];
            s = (u > 1.0f) ? 1.0f : 0.0f;
            o[(size_t)(t0 + i) * H_DIM] = s;
        }
        #pragma unroll
        for (int i = 0; i < U; i++)
            cur[i] = nxt[i];
    }
}

// ---------------------------------------------------------------------------
// Launch
// ---------------------------------------------------------------------------
extern "C" void kernel_launch(void* const* d_in, const int* in_sizes, int n_in,
                              void* d_out, int out_size)
{
    const float* x     = (const float*)d_in[0];  // [B, T, I]
    const float* W     = (const float*)d_in[1];  // [H, I]
    const float* alpha = (const float*)d_in[2];  // [H]
    const float* u0    = (const float*)d_in[3];  // [B, H]
    const float* s0    = (const float*)d_in[4];  // [B, H]
    float* out = (float*)d_out;                  // [B, T, H]

    (void)in_sizes; (void)n_in; (void)out_size;

    // GEMM: grid = (N/64, M/128) = (8, 512)
    dim3 ggrid(H_DIM / 64, M_DIM / 128);
    lif_gemm_kernel<<<ggrid, 256>>>(x, W);

    // Scan: 32 batches x 4 h-chunks = 128 CTAs of 128 threads
    lif_scan_kernel<<<B_DIM * 4, 128>>>(alpha, u0, s0, out);
}

// round 3
// speedup vs baseline: 1.3457x; 1.3457x over previous
#include <cuda_runtime.h>

// Problem dims (fixed for this problem instance)
#define B_DIM 32
#define T_DIM 2048
#define I_DIM 256
#define H_DIM 512
#define M_DIM (B_DIM * T_DIM)   // 65536

#define ALPHA_MIN_F 0.8187307530779818f   // exp(-1/5)
#define ALPHA_MAX_F 0.9607894391523232f   // exp(-1/25)

// Scratch for the feedforward projection Wx: [M, H] fp32 = 128 MiB
__device__ float g_wx[(size_t)M_DIM * H_DIM];

// ---------------------------------------------------------------------------
// GEMM: g_wx[m, h] = sum_k A[m, k] * W[h, k]   ("NT", K contiguous both sides)
// Tile: BM=128, BN=128, BK=16; 256 threads; each thread computes 8x8 outputs
// (split as 4x4 quadrants at rows {ty*4, 64+ty*4}, cols {tx*4, 64+tx*4} for
// conflict-free float4 LDS). Double-buffered smem + LDG prefetch.
// Accumulation order per output: k ascending (bitwise-identical to round 2).
// ---------------------------------------------------------------------------
__global__ __launch_bounds__(256) void lif_gemm_kernel(
    const float* __restrict__ A,
    const float* __restrict__ W)
{
    constexpr int BM = 128, BN = 128, BK = 16;
    __shared__ __align__(16) float As[2][BK][BM];
    __shared__ __align__(16) float Bs[2][BK][BN];

    const int tid = threadIdx.x;
    const int tx  = tid & 15;   // N direction
    const int ty  = tid >> 4;   // M direction

    const int m0 = blockIdx.y * BM;
    const int n0 = blockIdx.x * BN;

    // Global-load mapping: 128 rows x 16 k, 256 threads -> 2 float4 per thread
    const int lrow = tid >> 1;        // 0..127
    const int lk   = (tid & 1) * 8;   // 0 or 8

    const float* Aptr = A + (size_t)(m0 + lrow) * I_DIM + lk;
    const float* Wptr = W + (size_t)(n0 + lrow) * I_DIM + lk;

    float acc[8][8];
    #pragma unroll
    for (int i = 0; i < 8; i++)
        #pragma unroll
        for (int j = 0; j < 8; j++)
            acc[i][j] = 0.0f;

    // Preload tile 0
    float4 a0 = *(const float4*)(Aptr);
    float4 a1 = *(const float4*)(Aptr + 4);
    float4 b0 = *(const float4*)(Wptr);
    float4 b1 = *(const float4*)(Wptr + 4);

    int buf = 0;
    As[0][lk + 0][lrow] = a0.x; As[0][lk + 1][lrow] = a0.y;
    As[0][lk + 2][lrow] = a0.z; As[0][lk + 3][lrow] = a0.w;
    As[0][lk + 4][lrow] = a1.x; As[0][lk + 5][lrow] = a1.y;
    As[0][lk + 6][lrow] = a1.z; As[0][lk + 7][lrow] = a1.w;
    Bs[0][lk + 0][lrow] = b0.x; Bs[0][lk + 1][lrow] = b0.y;
    Bs[0][lk + 2][lrow] = b0.z; Bs[0][lk + 3][lrow] = b0.w;
    Bs[0][lk + 4][lrow] = b1.x; Bs[0][lk + 5][lrow] = b1.y;
    Bs[0][lk + 6][lrow] = b1.z; Bs[0][lk + 7][lrow] = b1.w;
    __syncthreads();

    constexpr int KO_N = I_DIM / BK;   // 16
    #pragma unroll 1
    for (int ko = 0; ko < KO_N; ko++) {
        // Prefetch next tile from GMEM (hidden behind the FMA block below)
        if (ko < KO_N - 1) {
            const float* Ap = Aptr + (ko + 1) * BK;
            const float* Wp = Wptr + (ko + 1) * BK;
            a0 = *(const float4*)(Ap);
            a1 = *(const float4*)(Ap + 4);
            b0 = *(const float4*)(Wp);
            b1 = *(const float4*)(Wp + 4);
        }

        #pragma unroll
        for (int k = 0; k < BK; k++) {
            float4 ra0 = *(const float4*)(&As[buf][k][ty * 4]);
            float4 ra1 = *(const float4*)(&As[buf][k][64 + ty * 4]);
            float4 rb0 = *(const float4*)(&Bs[buf][k][tx * 4]);
            float4 rb1 = *(const float4*)(&Bs[buf][k][64 + tx * 4]);
            float ra[8] = {ra0.x, ra0.y, ra0.z, ra0.w, ra1.x, ra1.y, ra1.z, ra1.w};
            float rb[8] = {rb0.x, rb0.y, rb0.z, rb0.w, rb1.x, rb1.y, rb1.z, rb1.w};
            #pragma unroll
            for (int i = 0; i < 8; i++)
                #pragma unroll
                for (int j = 0; j < 8; j++)
                    acc[i][j] += ra[i] * rb[j];
        }

        if (ko < KO_N - 1) {
            int nb = buf ^ 1;
            As[nb][lk + 0][lrow] = a0.x; As[nb][lk + 1][lrow] = a0.y;
            As[nb][lk + 2][lrow] = a0.z; As[nb][lk + 3][lrow] = a0.w;
            As[nb][lk + 4][lrow] = a1.x; As[nb][lk + 5][lrow] = a1.y;
            As[nb][lk + 6][lrow] = a1.z; As[nb][lk + 7][lrow] = a1.w;
            Bs[nb][lk + 0][lrow] = b0.x; Bs[nb][lk + 1][lrow] = b0.y;
            Bs[nb][lk + 2][lrow] = b0.z; Bs[nb][lk + 3][lrow] = b0.w;
            Bs[nb][lk + 4][lrow] = b1.x; Bs[nb][lk + 5][lrow] = b1.y;
            Bs[nb][lk + 6][lrow] = b1.z; Bs[nb][lk + 7][lrow] = b1.w;
            __syncthreads();
            buf = nb;
        }
    }

    // Epilogue: 8 rows x 2 float4 columns per thread
    #pragma unroll
    for (int i = 0; i < 8; i++) {
        int row = m0 + ((i < 4) ? (ty * 4 + i) : (64 + ty * 4 + i - 4));
        float* dst = &g_wx[(size_t)row * H_DIM + n0];
        *(float4*)(dst + tx * 4)      = make_float4(acc[i][0], acc[i][1], acc[i][2], acc[i][3]);
        *(float4*)(dst + 64 + tx * 4) = make_float4(acc[i][4], acc[i][5], acc[i][6], acc[i][7]);
    }
}

// ---------------------------------------------------------------------------
// Scan: one thread per (b, h) chain. Distance-2 software pipeline with 4
// rotating 16-element register buffers -> up to 32 outstanding loads/thread
// (2 MB in flight chip-wide -> ~4-6 TB/s effective). 64-thread CTAs spread
// 256 CTAs across all 148 SMs.
// ---------------------------------------------------------------------------
__global__ __launch_bounds__(64) void lif_scan_kernel(
    const float* __restrict__ alpha_in,
    const float* __restrict__ u0,
    const float* __restrict__ s0,
    float* __restrict__ out)
{
    const int b = blockIdx.x >> 3;                      // 0..31
    const int h = (blockIdx.x & 7) * 64 + threadIdx.x;  // 0..511

    float a = alpha_in[h];
    a = fminf(fmaxf(a, ALPHA_MIN_F), ALPHA_MAX_F);
    const float bc = 1.0f - a;

    float u = u0[b * H_DIM + h];
    float s = s0[b * H_DIM + h];

    const float* __restrict__ wx = g_wx + (size_t)b * T_DIM * H_DIM + h;
    float* __restrict__ o = out + (size_t)b * T_DIM * H_DIM + h;

    constexpr int U = 16;
    constexpr int NCH = T_DIM / U;   // 128 (divisible by 4)
    float buf[4][U];

    #pragma unroll
    for (int i = 0; i < U; i++)
        buf[0][i] = wx[(size_t)i * H_DIM];
    #pragma unroll
    for (int i = 0; i < U; i++)
        buf[1][i] = wx[(size_t)(U + i) * H_DIM];

    #pragma unroll 4
    for (int c = 0; c < NCH; c++) {
        // prefetch chunk c+2 (independent of recurrence)
        if (c + 2 < NCH) {
            const float* p = wx + (size_t)(c + 2) * U * H_DIM;
            #pragma unroll
            for (int i = 0; i < U; i++)
                buf[(c + 2) & 3][i] = p[(size_t)i * H_DIM];
        }
        // sequential LIF update on chunk c
        float* po = o + (size_t)c * U * H_DIM;
        #pragma unroll
        for (int i = 0; i < U; i++) {
            u = a * (u - s) + bc * buf[c & 3][i];
            s = (u > 1.0f) ? 1.0f : 0.0f;
            po[(size_t)i * H_DIM] = s;
        }
    }
}

// ---------------------------------------------------------------------------
// Launch
// ---------------------------------------------------------------------------
extern "C" void kernel_launch(void* const* d_in, const int* in_sizes, int n_in,
                              void* d_out, int out_size)
{
    const float* x     = (const float*)d_in[0];  // [B, T, I]
    const float* W     = (const float*)d_in[1];  // [H, I]
    const float* alpha = (const float*)d_in[2];  // [H]
    const float* u0    = (const float*)d_in[3];  // [B, H]
    const float* s0    = (const float*)d_in[4];  // [B, H]
    float* out = (float*)d_out;                  // [B, T, H]

    (void)in_sizes; (void)n_in; (void)out_size;

    // GEMM: grid = (N/128, M/128) = (4, 512)
    dim3 ggrid(H_DIM / 128, M_DIM / 128);
    lif_gemm_kernel<<<ggrid, 256>>>(x, W);

    // Scan: 32 batches x 8 h-chunks = 256 CTAs of 64 threads
    lif_scan_kernel<<<B_DIM * 8, 64>>>(alpha, u0, s0, out);
}

// round 4
// speedup vs baseline: 1.5112x; 1.1230x over previous
#include <cuda_runtime.h>
#include <cstdint>

// Problem dims (fixed for this problem instance)
#define B_DIM 32
#define T_DIM 2048
#define I_DIM 256
#define H_DIM 512
#define M_DIM (B_DIM * T_DIM)   // 65536

#define ALPHA_MIN_F 0.8187307530779818f   // exp(-1/5)
#define ALPHA_MAX_F 0.9607894391523232f   // exp(-1/25)

// Scratch: pre-scaled projection  g_wx[m,h] = (1-alpha_h) * (x @ W^T)[m,h]
__device__ float g_wx[(size_t)M_DIM * H_DIM];

// ---- packed f32x2 helpers (sm_103a; ptxas never auto-fuses FFMA2) ----------
__device__ __forceinline__ uint64_t pack2(float lo, float hi) {
    uint64_t r;
    asm("mov.b64 %0, {%1, %2};" : "=l"(r) : "f"(lo), "f"(hi));
    return r;
}
__device__ __forceinline__ void unpack2(uint64_t v, float& lo, float& hi) {
    asm("mov.b64 {%0, %1}, %2;" : "=f"(lo), "=f"(hi) : "l"(v));
}
__device__ __forceinline__ uint64_t ffma2(uint64_t a, uint64_t b, uint64_t c) {
    uint64_t d;
    asm("fma.rn.f32x2 %0, %1, %2, %3;" : "=l"(d) : "l"(a), "l"(b), "l"(c));
    return d;
}

// ---------------------------------------------------------------------------
// GEMM: wx[m, h] = sum_k A[m, k] * W[h, k]   ("NT", K contiguous both sides)
// BM=128, BN=128, BK=16; 256 threads; 8x8 outputs/thread computed as 8x4
// packed f32x2 accumulators (fma.rn.f32x2 -> 2x fp32 FMA issue throughput).
// Per-lane rounding == scalar FFMA, k ascending: wx bitwise-identical.
// Epilogue scales by bc[h] = 1 - clamp(alpha[h]).
// ---------------------------------------------------------------------------
__global__ __launch_bounds__(256, 2) void lif_gemm_kernel(
    const float* __restrict__ A,
    const float* __restrict__ W,
    const float* __restrict__ alpha_in)
{
    constexpr int BM = 128, BN = 128, BK = 16;
    __shared__ __align__(16) float As[2][BK][BM];
    __shared__ __align__(16) float Bs[2][BK][BN];

    const int tid = threadIdx.x;
    const int tx  = tid & 15;   // N direction
    const int ty  = tid >> 4;   // M direction

    const int m0 = blockIdx.y * BM;
    const int n0 = blockIdx.x * BN;

    // Global-load mapping: 128 rows x 16 k, 256 threads -> 2 float4 per thread
    const int lrow = tid >> 1;        // 0..127
    const int lk   = (tid & 1) * 8;   // 0 or 8

    const float* Aptr = A + (size_t)(m0 + lrow) * I_DIM + lk;
    const float* Wptr = W + (size_t)(n0 + lrow) * I_DIM + lk;

    uint64_t acc2[8][4];
    #pragma unroll
    for (int i = 0; i < 8; i++)
        #pragma unroll
        for (int j = 0; j < 4; j++)
            acc2[i][j] = 0ull;   // packed {0.0f, 0.0f}

    // Preload tile 0
    float4 a0 = *(const float4*)(Aptr);
    float4 a1 = *(const float4*)(Aptr + 4);
    float4 b0 = *(const float4*)(Wptr);
    float4 b1 = *(const float4*)(Wptr + 4);

    int buf = 0;
    As[0][lk + 0][lrow] = a0.x; As[0][lk + 1][lrow] = a0.y;
    As[0][lk + 2][lrow] = a0.z; As[0][lk + 3][lrow] = a0.w;
    As[0][lk + 4][lrow] = a1.x; As[0][lk + 5][lrow] = a1.y;
    As[0][lk + 6][lrow] = a1.z; As[0][lk + 7][lrow] = a1.w;
    Bs[0][lk + 0][lrow] = b0.x; Bs[0][lk + 1][lrow] = b0.y;
    Bs[0][lk + 2][lrow] = b0.z; Bs[0][lk + 3][lrow] = b0.w;
    Bs[0][lk + 4][lrow] = b1.x; Bs[0][lk + 5][lrow] = b1.y;
    Bs[0][lk + 6][lrow] = b1.z; Bs[0][lk + 7][lrow] = b1.w;
    __syncthreads();

    constexpr int KO_N = I_DIM / BK;   // 16
    #pragma unroll 1
    for (int ko = 0; ko < KO_N; ko++) {
        // Prefetch next tile from GMEM (hidden behind the FMA block below)
        if (ko < KO_N - 1) {
            const float* Ap = Aptr + (ko + 1) * BK;
            const float* Wp = Wptr + (ko + 1) * BK;
            a0 = *(const float4*)(Ap);
            a1 = *(const float4*)(Ap + 4);
            b0 = *(const float4*)(Wp);
            b1 = *(const float4*)(Wp + 4);
        }

        #pragma unroll
        for (int k = 0; k < BK; k++) {
            float4 ra0 = *(const float4*)(&As[buf][k][ty * 4]);
            float4 ra1 = *(const float4*)(&As[buf][k][64 + ty * 4]);
            float4 rb0 = *(const float4*)(&Bs[buf][k][tx * 4]);
            float4 rb1 = *(const float4*)(&Bs[buf][k][64 + tx * 4]);

            uint64_t bp[4];
            bp[0] = pack2(rb0.x, rb0.y);
            bp[1] = pack2(rb0.z, rb0.w);
            bp[2] = pack2(rb1.x, rb1.y);
            bp[3] = pack2(rb1.z, rb1.w);

            float ra[8] = {ra0.x, ra0.y, ra0.z, ra0.w,
                           ra1.x, ra1.y, ra1.z, ra1.w};
            #pragma unroll
            for (int i = 0; i < 8; i++) {
                uint64_t ad = pack2(ra[i], ra[i]);
                #pragma unroll
                for (int j = 0; j < 4; j++)
                    acc2[i][j] = ffma2(ad, bp[j], acc2[i][j]);
            }
        }

        if (ko < KO_N - 1) {
            int nb = buf ^ 1;
            As[nb][lk + 0][lrow] = a0.x; As[nb][lk + 1][lrow] = a0.y;
            As[nb][lk + 2][lrow] = a0.z; As[nb][lk + 3][lrow] = a0.w;
            As[nb][lk + 4][lrow] = a1.x; As[nb][lk + 5][lrow] = a1.y;
            As[nb][lk + 6][lrow] = a1.z; As[nb][lk + 7][lrow] = a1.w;
            Bs[nb][lk + 0][lrow] = b0.x; Bs[nb][lk + 1][lrow] = b0.y;
            Bs[nb][lk + 2][lrow] = b0.z; Bs[nb][lk + 3][lrow] = b0.w;
            Bs[nb][lk + 4][lrow] = b1.x; Bs[nb][lk + 5][lrow] = b1.y;
            Bs[nb][lk + 6][lrow] = b1.z; Bs[nb][lk + 7][lrow] = b1.w;
            __syncthreads();
            buf = nb;
        }
    }

    // Epilogue: scale by bc[h] = 1 - clamp(alpha[h]), then store
    float bcv[8];
    #pragma unroll
    for (int jj = 0; jj < 8; jj++) {
        int col = n0 + ((jj < 4) ? (tx * 4 + jj) : (64 + tx * 4 + (jj - 4)));
        float a = alpha_in[col];
        a = fminf(fmaxf(a, ALPHA_MIN_F), ALPHA_MAX_F);
        bcv[jj] = 1.0f - a;
    }

    #pragma unroll
    for (int i = 0; i < 8; i++) {
        int row = m0 + ((i < 4) ? (ty * 4 + i) : (64 + ty * 4 + (i - 4)));
        float c0, c1, c2, c3, c4, c5, c6, c7;
        unpack2(acc2[i][0], c0, c1);
        unpack2(acc2[i][1], c2, c3);
        unpack2(acc2[i][2], c4, c5);
        unpack2(acc2[i][3], c6, c7);
        float* dst = &g_wx[(size_t)row * H_DIM + n0];
        *(float4*)(dst + tx * 4) =
            make_float4(c0 * bcv[0], c1 * bcv[1], c2 * bcv[2], c3 * bcv[3]);
        *(float4*)(dst + 64 + tx * 4) =
            make_float4(c4 * bcv[4], c5 * bcv[5], c6 * bcv[6], c7 * bcv[7]);
    }
}

// ---------------------------------------------------------------------------
// Scan: one thread per (b, h) chain. Distance-3 software pipeline (48
// outstanding loads/thread). Steady-state step keeps the spike as a
// predicate: um = p ? (u - 1.0f) : u;  u = fma(a, um, w);  p = u > 1.
// Bitwise-identical to the float-s formulation (u-1.0f == u-s for s=1,
// u-0.0f == u). First chunk peeled with general float-s math since s0 is a
// non-binary uniform random.
// ---------------------------------------------------------------------------
__global__ __launch_bounds__(64) void lif_scan_kernel(
    const float* __restrict__ alpha_in,
    const float* __restrict__ u0,
    const float* __restrict__ s0,
    float* __restrict__ out)
{
    const int b = blockIdx.x >> 3;                      // 0..31
    const int h = (blockIdx.x & 7) * 64 + threadIdx.x;  // 0..511

    float a = alpha_in[h];
    a = fminf(fmaxf(a, ALPHA_MIN_F), ALPHA_MAX_F);

    float u = u0[b * H_DIM + h];
    float s = s0[b * H_DIM + h];

    const float* __restrict__ wx = g_wx + (size_t)b * T_DIM * H_DIM + h;
    float* __restrict__ o = out + (size_t)b * T_DIM * H_DIM + h;

    constexpr int U = 16;
    constexpr int NCH = T_DIM / U;   // 128
    float buf[4][U];

    // Prologue: issue loads for chunks 0, 1, 2
    #pragma unroll
    for (int c0 = 0; c0 < 3; c0++) {
        const float* p = wx + (size_t)c0 * U * H_DIM;
        #pragma unroll
        for (int i = 0; i < U; i++)
            buf[c0][i] = p[(size_t)i * H_DIM];
    }

    // ---- chunk 0: general float-s form (s0 is arbitrary float) ----
    {
        // prefetch chunk 3
        const float* p = wx + (size_t)3 * U * H_DIM;
        #pragma unroll
        for (int i = 0; i < U; i++)
            buf[3][i] = p[(size_t)i * H_DIM];

        #pragma unroll
        for (int i = 0; i < U; i++) {
            u = a * (u - s) + buf[0][i];            // buf already = bc*wx
            s = (u > 1.0f) ? 1.0f : 0.0f;
            o[(size_t)i * H_DIM] = s;
        }
    }
    bool pr = (s != 0.0f);

    // ---- chunks 1..127: predicate form, distance-3 prefetch ----
    #pragma unroll 4
    for (int c = 1; c < NCH; c++) {
        if (c + 3 < NCH) {
            const float* p = wx + (size_t)(c + 3) * U * H_DIM;
            #pragma unroll
            for (int i = 0; i < U; i++)
                buf[(c + 3) & 3][i] = p[(size_t)i * H_DIM];
        }
        float* po = o + (size_t)c * U * H_DIM;
        #pragma unroll
        for (int i = 0; i < U; i++) {
            float w  = buf[c & 3][i];
            float d  = u - 1.0f;
            float um = pr ? d : u;
            u  = fmaf(a, um, w);
            pr = (u > 1.0f);
            po[(size_t)i * H_DIM] = pr ? 1.0f : 0.0f;
        }
    }
}

// ---------------------------------------------------------------------------
// Launch
// ---------------------------------------------------------------------------
extern "C" void kernel_launch(void* const* d_in, const int* in_sizes, int n_in,
                              void* d_out, int out_size)
{
    const float* x     = (const float*)d_in[0];  // [B, T, I]
    const float* W     = (const float*)d_in[1];  // [H, I]
    const float* alpha = (const float*)d_in[2];  // [H]
    const float* u0    = (const float*)d_in[3];  // [B, H]
    const float* s0    = (const float*)d_in[4];  // [B, H]
    float* out = (float*)d_out;                  // [B, T, H]

    (void)in_sizes; (void)n_in; (void)out_size;

    // GEMM: grid = (N/128, M/128) = (4, 512)
    dim3 ggrid(H_DIM / 128, M_DIM / 128);
    lif_gemm_kernel<<<ggrid, 256>>>(x, W, alpha);

    // Scan: 32 batches x 8 h-chunks = 256 CTAs of 64 threads
    lif_scan_kernel<<<B_DIM * 8, 64>>>(alpha, u0, s0, out);
}